// round 3
// baseline (speedup 1.0000x reference)
#include <cuda_runtime.h>

#define B_ 32
#define M_ 2048
#define H_ 1024
#define NTOK (B_*M_)
#define THRESH 0.99f

// Scratch (no allocations allowed).
__device__ int g_rank[NTOK];          // clip(cumsum(run)-1, 0, M-1)
__device__ unsigned char g_runb[NTOK];// decoded run mask
__device__ int g_src[NTOK];           // run_new ? rank : -1
__device__ int g_gidx[NTOK];          // packed row d -> source row in h, -1 => zero row

// ---------------------------------------------------------------------------
// K0: wire-format probe + decode + per-batch rank scan, fused.
// Probe: read this block's 512-word window of `run` as u32. int32 {0,1} =>
// no high bytes anywhere; u8 bools (~50% ones) => high bytes with
// probability 1 - 2^-1536. Window [b*512,(b+1)*512) words stays inside the
// 64KB u8 buffer for all b.
// ---------------------------------------------------------------------------
__global__ void rank_kernel(const void* __restrict__ run) {
    const int b = blockIdx.x;
    const int t = threadIdx.x;            // 256 threads
    const unsigned int* w = (const unsigned int*)run;

    int found = 0;
    #pragma unroll
    for (int i = 0; i < 2; i++)
        if (w[b * 512 + i * 256 + t] & 0xFFFFFF00u) found = 1;
    const int fmt_u8 = __syncthreads_or(found);

    const unsigned char* ru8 = (const unsigned char*)run + b * M_;
    const int* ri32 = (const int*)run + b * M_;
    const int base = t * 8;

    int v[8];
    int s = 0;
    #pragma unroll
    for (int i = 0; i < 8; i++) {
        v[i] = fmt_u8 ? (ru8[base + i] != 0) : (ri32[base + i] != 0);
        s += v[i];
        g_runb[b * M_ + base + i] = (unsigned char)v[i];
    }

    const int lane = t & 31, warp = t >> 5;
    int x = s;  // inclusive warp scan of per-thread sums
    #pragma unroll
    for (int o = 1; o < 32; o <<= 1) {
        int y = __shfl_up_sync(0xffffffffu, x, o);
        if (lane >= o) x += y;
    }
    __shared__ int wsum[8], woff[8];
    if (lane == 31) wsum[warp] = x;
    __syncthreads();
    if (t == 0) { int a = 0; for (int i = 0; i < 8; i++) { woff[i] = a; a += wsum[i]; } }
    __syncthreads();

    int c = woff[warp] + (x - s);
    #pragma unroll
    for (int i = 0; i < 8; i++) {
        c += v[i];
        int rk = c - 1;
        if (rk < 0) rk = 0;
        g_rank[b * M_ + base + i] = rk;
    }
}

// ---------------------------------------------------------------------------
// K1: warp-per-token. Dot(h[rank], W) -> sigmoid -> halting scalars ->
// weighted_new blend reusing the registers. Streaming operands (wh in,
// weighted out) use evict-first hints so h lines stay resident in L2 for
// the pack gather that follows.
// ---------------------------------------------------------------------------
__global__ __launch_bounds__(256) void main_kernel(
    const float* __restrict__ h, const float* __restrict__ W,
    const float* __restrict__ bias, const float* __restrict__ wh,
    const float* __restrict__ accp,
    float* __restrict__ weighted_out, float* __restrict__ acc_out)
{
    __shared__ float sW[H_];
    ((float4*)sW)[threadIdx.x] = ((const float4*)W)[threadIdx.x];
    __syncthreads();

    const int warp = threadIdx.x >> 5, lane = threadIdx.x & 31;
    const int tok = blockIdx.x * 8 + warp;
    const int b = tok >> 11;
    const bool running = g_runb[tok] != 0;
    const int rank = g_rank[tok];

    float4 hv[8];
    float dot = 0.0f;
    if (running) {
        const float4* hrow = (const float4*)(h + ((size_t)b * M_ + rank) * H_);
        #pragma unroll
        for (int i = 0; i < 8; i++) {
            float4 a = hrow[lane + i * 32];   // default cache: keep in L2 for pack
            hv[i] = a;
            float4 wv = ((const float4*)sW)[lane + i * 32];
            dot += a.x * wv.x;
            dot += a.y * wv.y;
            dot += a.z * wv.z;
            dot += a.w * wv.w;
        }
    } else {
        #pragma unroll
        for (int i = 0; i < 8; i++) hv[i] = make_float4(0.f, 0.f, 0.f, 0.f);
    }
    #pragma unroll
    for (int o = 16; o > 0; o >>= 1)
        dot += __shfl_xor_sync(0xffffffffu, dot, o);

    float acc = accp[tok];
    float p_adj = 0.0f;
    bool run_new = false;
    if (running) {
        float z = dot + bias[0];
        float p = 1.0f / (1.0f + expf(-z));
        float acc_new = acc + p;
        run_new = acc_new < THRESH;
        p_adj = run_new ? p : (1.0f - (acc_new - p));
        acc = acc_new;
    }
    if (lane == 0) {
        acc_out[tok] = acc;
        g_src[tok] = run_new ? rank : -1;
    }

    const float4* whrow = (const float4*)(wh + (size_t)tok * H_);
    float4* wo = (float4*)(weighted_out + (size_t)tok * H_);
    const float q = 1.0f - p_adj;
    #pragma unroll
    for (int i = 0; i < 8; i++) {
        float4 w4 = __ldcs(whrow + lane + i * 32);   // streaming read
        float4 o4;
        o4.x = hv[i].x * p_adj + w4.x * q;
        o4.y = hv[i].y * p_adj + w4.y * q;
        o4.z = hv[i].z * p_adj + w4.z * q;
        o4.w = hv[i].w * p_adj + w4.w * q;
        __stcs(wo + lane + i * 32, o4);              // streaming write
    }
}

// ---------------------------------------------------------------------------
// K2: per-batch stable compaction: gidx[dest] = rank[src] for run_new tokens.
// ---------------------------------------------------------------------------
__global__ void compact_kernel() {
    const int b = blockIdx.x;
    const int t = threadIdx.x;  // 256
    const int base = b * M_ + t * 8;

    int src[8], v[8];
    int s = 0;
    int4 s0 = ((const int4*)(g_src + base))[0];
    int4 s1 = ((const int4*)(g_src + base))[1];
    src[0]=s0.x; src[1]=s0.y; src[2]=s0.z; src[3]=s0.w;
    src[4]=s1.x; src[5]=s1.y; src[6]=s1.z; src[7]=s1.w;
    #pragma unroll
    for (int i = 0; i < 8; i++) {
        v[i] = (src[i] >= 0) ? 1 : 0;
        s += v[i];
        g_gidx[base + i] = -1;   // default: zero row
    }

    const int lane = t & 31, warp = t >> 5;
    int x = s;
    #pragma unroll
    for (int o = 1; o < 32; o <<= 1) {
        int y = __shfl_up_sync(0xffffffffu, x, o);
        if (lane >= o) x += y;
    }
    __shared__ int wsum[8], woff[8];
    if (lane == 31) wsum[warp] = x;
    __syncthreads();
    if (t == 0) { int a = 0; for (int i = 0; i < 8; i++) { woff[i] = a; a += wsum[i]; } }
    __syncthreads();   // also orders the -1 init before scatter

    int pos = woff[warp] + (x - s);
    #pragma unroll
    for (int i = 0; i < 8; i++) {
        if (v[i]) {
            g_gidx[b * M_ + pos] = src[i];
            pos++;
        }
    }
}

// ---------------------------------------------------------------------------
// K3: packed[b,d,:] = gidx>=0 ? h[b,gidx,:] : 0. Warp-per-row gather.
// h reads are last-use (evict-first); packed writes streaming.
// ---------------------------------------------------------------------------
__global__ __launch_bounds__(256) void pack_kernel(const float* __restrict__ h,
                                                   float* __restrict__ packed)
{
    const int warp = threadIdx.x >> 5, lane = threadIdx.x & 31;
    const int tok = blockIdx.x * 8 + warp;
    const int b = tok >> 11;
    const int g = g_gidx[tok];

    float4* out = (float4*)(packed + (size_t)tok * H_);
    if (g >= 0) {
        const float4* hrow = (const float4*)(h + ((size_t)b * M_ + g) * H_);
        #pragma unroll
        for (int i = 0; i < 8; i++)
            __stcs(out + lane + i * 32, __ldcs(hrow + lane + i * 32));
    } else {
        const float4 z = make_float4(0.f, 0.f, 0.f, 0.f);
        #pragma unroll
        for (int i = 0; i < 8; i++)
            __stcs(out + lane + i * 32, z);
    }
}

// ---------------------------------------------------------------------------
extern "C" void kernel_launch(void* const* d_in, const int* in_sizes, int n_in,
                              void* d_out, int out_size) {
    const float* h    = (const float*)d_in[0];
    const float* W    = (const float*)d_in[1];
    const float* bias = (const float*)d_in[2];
    const float* wh   = (const float*)d_in[3];
    const float* accp = (const float*)d_in[4];
    const void*  run  = d_in[5];

    float* out      = (float*)d_out;
    float* packed   = out;                              // [B,M,H]
    float* weighted = out + (size_t)NTOK * H_;          // [B,M,H]
    float* acc      = out + 2 * (size_t)NTOK * H_;      // [B,M,1]

    rank_kernel<<<B_, 256>>>(run);
    main_kernel<<<NTOK / 8, 256>>>(h, W, bias, wh, accp, weighted, acc);
    compact_kernel<<<B_, 256>>>();
    pack_kernel<<<NTOK / 8, 256>>>(h, packed);
}

// round 4
// speedup vs baseline: 1.0718x; 1.0718x over previous
#include <cuda_runtime.h>

#define B_ 32
#define M_ 2048
#define H_ 1024
#define NTOK (B_*M_)
#define THRESH 0.99f
#define BLOCKS_PER_BATCH (M_/4)   // main: 4 tokens per block

// Scratch (no allocations allowed).
__device__ int g_rank[NTOK];          // clip(cumsum(run)-1, 0, M-1)
__device__ unsigned char g_runb[NTOK];// decoded run mask
__device__ int g_src[NTOK];           // run_new ? rank : -1
__device__ int g_gidx[NTOK];          // packed row d -> source row in h, -1 => zero row
__device__ int g_done[B_];            // per-batch completion counters (reset each call)

// ---------------------------------------------------------------------------
// K0: wire-format probe + decode + per-batch rank scan, fused. Also resets
// this batch's g_done counter for the fused compaction in main_kernel.
// Probe: read this block's 512-word window of `run` as u32. int32 {0,1} =>
// no bits above the low byte anywhere; u8 bools (~50% ones) => high bytes
// present with probability 1 - 2^-1536.
// ---------------------------------------------------------------------------
__global__ void rank_kernel(const void* __restrict__ run) {
    const int b = blockIdx.x;
    const int t = threadIdx.x;            // 256 threads
    const unsigned int* w = (const unsigned int*)run;

    if (t == 0) g_done[b] = 0;

    int found = 0;
    #pragma unroll
    for (int i = 0; i < 2; i++)
        if (w[b * 512 + i * 256 + t] & 0xFFFFFF00u) found = 1;
    const int fmt_u8 = __syncthreads_or(found);

    const unsigned char* ru8 = (const unsigned char*)run + b * M_;
    const int* ri32 = (const int*)run + b * M_;
    const int base = t * 8;

    int v[8];
    int s = 0;
    #pragma unroll
    for (int i = 0; i < 8; i++) {
        v[i] = fmt_u8 ? (ru8[base + i] != 0) : (ri32[base + i] != 0);
        s += v[i];
        g_runb[b * M_ + base + i] = (unsigned char)v[i];
    }

    const int lane = t & 31, warp = t >> 5;
    int x = s;  // inclusive warp scan of per-thread sums
    #pragma unroll
    for (int o = 1; o < 32; o <<= 1) {
        int y = __shfl_up_sync(0xffffffffu, x, o);
        if (lane >= o) x += y;
    }
    __shared__ int wsum[8], woff[8];
    if (lane == 31) wsum[warp] = x;
    __syncthreads();
    if (t == 0) { int a = 0; for (int i = 0; i < 8; i++) { woff[i] = a; a += wsum[i]; } }
    __syncthreads();

    int c = woff[warp] + (x - s);
    #pragma unroll
    for (int i = 0; i < 8; i++) {
        c += v[i];
        int rk = c - 1;
        if (rk < 0) rk = 0;
        g_rank[b * M_ + base + i] = rk;
    }
}

// ---------------------------------------------------------------------------
// K1: warp-per-token (4 warps / 128 threads per block, R2 shape — no cache
// hints). Dot(h[rank], W) -> sigmoid -> halting scalars -> weighted_new
// blend from registers. Tail: last block per batch runs that batch's stable
// compaction (g_src -> g_gidx), removing the separate compact launch.
// ---------------------------------------------------------------------------
__global__ __launch_bounds__(128) void main_kernel(
    const float* __restrict__ h, const float* __restrict__ W,
    const float* __restrict__ bias, const float* __restrict__ wh,
    const float* __restrict__ accp,
    float* __restrict__ weighted_out, float* __restrict__ acc_out)
{
    __shared__ float sW[H_];
    for (int i = threadIdx.x; i < H_ / 4; i += 128)
        ((float4*)sW)[i] = ((const float4*)W)[i];
    __syncthreads();

    const int warp = threadIdx.x >> 5, lane = threadIdx.x & 31;
    const int tok = blockIdx.x * 4 + warp;
    const int b = tok >> 11;               // uniform per block (4 | 2048)
    const bool running = g_runb[tok] != 0;
    const int rank = g_rank[tok];

    float4 hv[8];
    float dot = 0.0f;
    if (running) {
        const float4* hrow = (const float4*)(h + ((size_t)b * M_ + rank) * H_);
        #pragma unroll
        for (int i = 0; i < 8; i++) {
            float4 a = hrow[lane + i * 32];
            hv[i] = a;
            float4 wv = ((const float4*)sW)[lane + i * 32];
            dot += a.x * wv.x;
            dot += a.y * wv.y;
            dot += a.z * wv.z;
            dot += a.w * wv.w;
        }
    } else {
        #pragma unroll
        for (int i = 0; i < 8; i++) hv[i] = make_float4(0.f, 0.f, 0.f, 0.f);
    }
    #pragma unroll
    for (int o = 16; o > 0; o >>= 1)
        dot += __shfl_xor_sync(0xffffffffu, dot, o);

    float acc = accp[tok];
    float p_adj = 0.0f;
    bool run_new = false;
    if (running) {
        float z = dot + bias[0];
        float p = 1.0f / (1.0f + expf(-z));
        float acc_new = acc + p;
        run_new = acc_new < THRESH;
        p_adj = run_new ? p : (1.0f - (acc_new - p));
        acc = acc_new;
    }
    if (lane == 0) {
        acc_out[tok] = acc;
        g_src[tok] = run_new ? rank : -1;
    }

    const float4* whrow = (const float4*)(wh + (size_t)tok * H_);
    float4* wo = (float4*)(weighted_out + (size_t)tok * H_);
    const float q = 1.0f - p_adj;
    #pragma unroll
    for (int i = 0; i < 8; i++) {
        float4 w4 = whrow[lane + i * 32];
        float4 o4;
        o4.x = hv[i].x * p_adj + w4.x * q;
        o4.y = hv[i].y * p_adj + w4.y * q;
        o4.z = hv[i].z * p_adj + w4.z * q;
        o4.w = hv[i].w * p_adj + w4.w * q;
        wo[lane + i * 32] = o4;
    }

    // ---- fused per-batch compaction: last-arriving block does the scan ----
    __shared__ int s_last;
    __syncthreads();                 // all warps' g_src writes issued
    if (threadIdx.x == 0) {
        __threadfence();             // release g_src to other SMs
        int n = atomicAdd(&g_done[b], 1);
        s_last = (n == BLOCKS_PER_BATCH - 1);
    }
    __syncthreads();
    if (!s_last) return;

    // This block compacts batch b: 2048 elements, 128 threads, 16 per thread.
    const int t = threadIdx.x;
    const int base = b * M_ + t * 16;
    int src[16], v[16];
    int s = 0;
    #pragma unroll
    for (int i = 0; i < 16; i++) {
        src[i] = g_src[base + i];
        v[i] = (src[i] >= 0) ? 1 : 0;
        s += v[i];
        g_gidx[base + i] = -1;       // default: zero row
    }
    int x = s;
    #pragma unroll
    for (int o = 1; o < 32; o <<= 1) {
        int y = __shfl_up_sync(0xffffffffu, x, o);
        if (lane >= o) x += y;
    }
    __shared__ int cw[4], co[4];
    if (lane == 31) cw[warp] = x;
    __syncthreads();
    if (t == 0) { int a = 0; for (int i = 0; i < 4; i++) { co[i] = a; a += cw[i]; } }
    __syncthreads();                 // also orders the -1 init before scatter

    int pos = co[warp] + (x - s);    // exclusive prefix = destination slot
    #pragma unroll
    for (int i = 0; i < 16; i++) {
        if (v[i]) {
            g_gidx[b * M_ + pos] = src[i];
            pos++;
        }
    }
}

// ---------------------------------------------------------------------------
// K3: packed[b,d,:] = gidx>=0 ? h[b,gidx,:] : 0. Warp-per-row gather,
// R2 shape (128 threads, no cache hints).
// ---------------------------------------------------------------------------
__global__ __launch_bounds__(128) void pack_kernel(const float* __restrict__ h,
                                                   float* __restrict__ packed)
{
    const int warp = threadIdx.x >> 5, lane = threadIdx.x & 31;
    const int tok = blockIdx.x * 4 + warp;
    const int b = tok >> 11;
    const int g = g_gidx[tok];

    float4* out = (float4*)(packed + (size_t)tok * H_);
    if (g >= 0) {
        const float4* hrow = (const float4*)(h + ((size_t)b * M_ + g) * H_);
        #pragma unroll
        for (int i = 0; i < 8; i++) out[lane + i * 32] = hrow[lane + i * 32];
    } else {
        const float4 z = make_float4(0.f, 0.f, 0.f, 0.f);
        #pragma unroll
        for (int i = 0; i < 8; i++) out[lane + i * 32] = z;
    }
}

// ---------------------------------------------------------------------------
extern "C" void kernel_launch(void* const* d_in, const int* in_sizes, int n_in,
                              void* d_out, int out_size) {
    const float* h    = (const float*)d_in[0];
    const float* W    = (const float*)d_in[1];
    const float* bias = (const float*)d_in[2];
    const float* wh   = (const float*)d_in[3];
    const float* accp = (const float*)d_in[4];
    const void*  run  = d_in[5];

    float* out      = (float*)d_out;
    float* packed   = out;                              // [B,M,H]
    float* weighted = out + (size_t)NTOK * H_;          // [B,M,H]
    float* acc      = out + 2 * (size_t)NTOK * H_;      // [B,M,1]

    rank_kernel<<<B_, 256>>>(run);
    main_kernel<<<NTOK / 4, 128>>>(h, W, bias, wh, accp, weighted, acc);
    pack_kernel<<<NTOK / 4, 128>>>(h, packed);
}